// round 5
// baseline (speedup 1.0000x reference)
#include <cuda_runtime.h>
#include <math.h>
#include <float.h>

#define NN     1500
#define NQ     375          // NN/4
#define GIN    32
#define GOUT   8
#define HID    128
#define CAP    128          // max nnz per combined-adjacency row (mean ~60)
#define LALPHA 0.2f
#define STR    68           // k_pairs smem row stride (floats)
#define NBLK   148          // persistent kernel: one block per SM (one wave)
#define NTHR   256
#define NWARPS (NBLK * (NTHR / 32))

typedef unsigned long long ull;

// ---------------- scratch (device globals) ----------------------------------
__device__ int      g_cnt[NN];
__device__ unsigned g_cols[NN * CAP];       // col | (a==2 ? bit31 : 0)
__device__ float    g_enc[NN * GOUT];       // final GAT output
__device__ float    g_h[2][NN * GOUT];      // ping-pong transformed feats
__device__ float    g_fsrc[2][NN];
__device__ float    g_fdst[2][NN];
__device__ float    g_u[NN * HID];          // enc[i] @ fc1_w[0:8] + b
__device__ float    g_v[NN * HID];          // enc[j] @ fc1_w[8:16]
__device__ int          g_barcnt;
__device__ volatile int g_barflag;

// ---------------- grid barrier (persistent, generation-flag) ----------------
// All NBLK blocks are co-resident (grid == SM count). Generations 1..4 per
// launch; flag ends at 4, next launch's first wait is for 1, so stale state
// can never satisfy a wait early. Counter returns to 0 every barrier.
__device__ __forceinline__ void gridbar(int gen) {
    __syncthreads();
    if (threadIdx.x == 0) {
        __threadfence();
        if (atomicAdd(&g_barcnt, 1) == NBLK - 1) {
            g_barcnt = 0;
            __threadfence();
            g_barflag = gen;
        } else {
            while (g_barflag != gen) { }
        }
        __threadfence();
    }
    __syncthreads();
}

// ---------------- f32x2 packed helpers --------------------------------------
__device__ __forceinline__ ull f2_pack(float lo, float hi) {
    ull r; asm("mov.b64 %0, {%1, %2};" : "=l"(r) : "f"(lo), "f"(hi)); return r;
}
__device__ __forceinline__ ull f2_add(ull a, ull b) {
    ull r; asm("add.rn.f32x2 %0, %1, %2;" : "=l"(r) : "l"(a), "l"(b)); return r;
}
__device__ __forceinline__ ull f2_fma(ull a, ull b, ull c) {
    ull r; asm("fma.rn.f32x2 %0, %1, %2, %3;" : "=l"(r) : "l"(a), "l"(b), "l"(c)); return r;
}
__device__ __forceinline__ void relu_acc(ull p, float c, float& a0, float& a1) {
    float lo = __uint_as_float((unsigned)p);
    float hi = __uint_as_float((unsigned)(p >> 32));
    a0 = fmaf(fmaxf(lo, 0.f), c, a0);
    a1 = fmaf(fmaxf(hi, 0.f), c, a1);
}

// ---------------- sparse GAT layer body (warp per row) ----------------------
template <bool LAST>
__device__ __forceinline__ void gats_row(int i, int lane, int hsrc, int hdst,
                                         const float* __restrict__ Wn,
                                         const float* __restrict__ an) {
    const float fsrc = g_fsrc[hsrc][i];
    const float* __restrict__ fdst = g_fdst[hsrc];
    const float* __restrict__ hbuf = g_h[hsrc];
    const int cnt = g_cnt[i];
    const unsigned* __restrict__ cols = g_cols + (size_t)i * CAP;

    float e[4]; int jj[4];
    float m = -FLT_MAX;
#pragma unroll
    for (int k = 0; k < 4; k++) {
        int idx = lane + k * 32;
        jj[k] = -1; e[k] = 0.f;
        if (idx < cnt) {
            unsigned pc = cols[idx];
            int j = pc & 0x7FFFFFFF;
            float a = (pc & 0x80000000u) ? 2.f : 1.f;
            float t = fsrc + fdst[j];
            float le = (t > 0.f ? t : LALPHA * t) * a;
            e[k] = le; jj[k] = j;
            m = fmaxf(m, le);
        }
    }
#pragma unroll
    for (int o = 16; o > 0; o >>= 1)
        m = fmaxf(m, __shfl_xor_sync(0xFFFFFFFFu, m, o));

    float s = 0.f, acc[GOUT];
#pragma unroll
    for (int q = 0; q < GOUT; q++) acc[q] = 0.f;
#pragma unroll
    for (int k = 0; k < 4; k++) {
        if (jj[k] >= 0) {
            float p = expf(e[k] - m);
            s += p;
            const float4* hp = reinterpret_cast<const float4*>(hbuf + jj[k] * GOUT);
            float4 h0 = hp[0], h1 = hp[1];
            acc[0] = fmaf(p, h0.x, acc[0]); acc[1] = fmaf(p, h0.y, acc[1]);
            acc[2] = fmaf(p, h0.z, acc[2]); acc[3] = fmaf(p, h0.w, acc[3]);
            acc[4] = fmaf(p, h1.x, acc[4]); acc[5] = fmaf(p, h1.y, acc[5]);
            acc[6] = fmaf(p, h1.z, acc[6]); acc[7] = fmaf(p, h1.w, acc[7]);
        }
    }
#pragma unroll
    for (int o = 16; o > 0; o >>= 1) {
        s += __shfl_xor_sync(0xFFFFFFFFu, s, o);
#pragma unroll
        for (int q = 0; q < GOUT; q++)
            acc[q] += __shfl_xor_sync(0xFFFFFFFFu, acc[q], o);
    }

    float inv = 1.f / s;
    float enc[GOUT];
#pragma unroll
    for (int q = 0; q < GOUT; q++) {
        float v = acc[q] * inv;
        enc[q] = (v > 0.f) ? v : expm1f(v);   // elu
    }

    if (LAST) {
        if (lane < GOUT) g_enc[i * GOUT + lane] = enc[lane];
    } else {
        if (lane < GOUT) {
            float hn = 0.f;
#pragma unroll
            for (int k = 0; k < GOUT; k++)
                hn = fmaf(enc[k], Wn[k * GOUT + lane], hn);
            g_h[hdst][i * GOUT + lane] = hn;
            float fs = hn * an[lane];
            float fd = hn * an[GOUT + lane];
#pragma unroll
            for (int o = 4; o > 0; o >>= 1) {
                fs += __shfl_xor_sync(0x000000FFu, fs, o);
                fd += __shfl_xor_sync(0x000000FFu, fd, o);
            }
            if (lane == 0) { g_fsrc[hdst][i] = fs; g_fdst[hdst][i] = fd; }
        }
    }
}

// ---------------- fused graph kernel: build + t0 + 3x GAT + prep ------------
__global__ __launch_bounds__(NTHR, 1) void k_fused(
        const float4* __restrict__ geo, const float4* __restrict__ sem,
        const float* __restrict__ feats,
        const float* __restrict__ W0, const float* __restrict__ a0,
        const float* __restrict__ W1, const float* __restrict__ a1,
        const float* __restrict__ W2, const float* __restrict__ a2,
        const float* __restrict__ fc1_w, const float* __restrict__ fc1_b) {
    const int lane = threadIdx.x & 31;
    const int wgid = blockIdx.x * (NTHR / 32) + (threadIdx.x >> 5);

    // --- P0: build CSR (warp per row) + layer-0 transform -------------------
    for (int i = wgid; i < NN; i += NWARPS) {
        const float4* g = geo + (size_t)i * NQ;
        const float4* s = sem + (size_t)i * NQ;
        unsigned* dst = g_cols + (size_t)i * CAP;
        int base = 0;
#pragma unroll
        for (int c = 0; c < 12; c++) {
            int f = c * 32 + lane;
            float v[4];
            int cntl = 0;
            bool ok = (f < NQ);
            if (ok) {
                float4 a = g[f], b = s[f];
                v[0] = a.x + b.x; v[1] = a.y + b.y;
                v[2] = a.z + b.z; v[3] = a.w + b.w;
                cntl = (v[0] > 0.f) + (v[1] > 0.f) + (v[2] > 0.f) + (v[3] > 0.f);
            }
            int x = cntl;
#pragma unroll
            for (int o = 1; o < 32; o <<= 1) {
                int y = __shfl_up_sync(0xFFFFFFFFu, x, o);
                if (lane >= o) x += y;
            }
            int off = base + x - cntl;           // exclusive prefix
            base += __shfl_sync(0xFFFFFFFFu, x, 31);
            if (ok) {
#pragma unroll
                for (int k = 0; k < 4; k++) {
                    if (v[k] > 0.f) {
                        if (off < CAP)
                            dst[off] = (unsigned)(f * 4 + k) |
                                       (v[k] >= 1.5f ? 0x80000000u : 0u);
                        off++;
                    }
                }
            }
        }
        if (lane == 0) g_cnt[i] = min(base, CAP);

        // layer-0 transform: lanes 0-7, one output channel each
        if (lane < GOUT) {
            float acc = 0.f;
#pragma unroll
            for (int k = 0; k < GIN; k++)
                acc = fmaf(feats[i * GIN + k], W0[k * GOUT + lane], acc);
            g_h[0][i * GOUT + lane] = acc;
            float fs = acc * a0[lane];
            float fd = acc * a0[GOUT + lane];
#pragma unroll
            for (int o = 4; o > 0; o >>= 1) {
                fs += __shfl_xor_sync(0x000000FFu, fs, o);
                fd += __shfl_xor_sync(0x000000FFu, fd, o);
            }
            if (lane == 0) { g_fsrc[0][i] = fs; g_fdst[0][i] = fd; }
        }
    }
    gridbar(1);

    // --- P1/P2/P3: GAT layers ------------------------------------------------
    for (int i = wgid; i < NN; i += NWARPS) gats_row<false>(i, lane, 0, 1, W1, a1);
    gridbar(2);
    for (int i = wgid; i < NN; i += NWARPS) gats_row<false>(i, lane, 1, 0, W2, a2);
    gridbar(3);
    for (int i = wgid; i < NN; i += NWARPS) gats_row<true>(i, lane, 0, 1, nullptr, nullptr);
    gridbar(4);

    // --- P4: pair-MLP rank-split precompute ----------------------------------
    const int gtid = blockIdx.x * NTHR + threadIdx.x;
    for (int idx = gtid; idx < NN * HID; idx += NBLK * NTHR) {
        int i = idx >> 7, h = idx & 127;
        const float* enc = g_enc + i * GOUT;
        float u = fc1_b[h], v = 0.f;
#pragma unroll
        for (int k = 0; k < GOUT; k++) {
            float e = enc[k];
            u = fmaf(e, fc1_w[k * HID + h], u);
            v = fmaf(e, fc1_w[(GOUT + k) * HID + h], v);
        }
        g_u[idx] = u;
        g_v[idx] = v;
    }
}

// ---------------- pair MLP: out = relu(u_i + v_j + d*w) . c + b -------------
// 32 i-rows x 64 j-cols per CTA, 256 threads, 2x4 pairs/thread, f32x2 packed
// for (u+v) and the d*w FMA; scalar FMNMX/FFMA for relu-accumulate.
// (w,w,c) packed in one 16B smem word -> 3 LDS per h-iter.
__global__ __launch_bounds__(256) void k_pairs(const float* __restrict__ dist,
                                               const float* __restrict__ fc1_w,
                                               const float* __restrict__ fc2_w,
                                               const float* __restrict__ fc2_b,
                                               float* __restrict__ out) {
    extern __shared__ __align__(16) char smem_raw[];
    float*  us  = reinterpret_cast<float*>(smem_raw);        // [HID][STR] dup'd
    float*  vs  = us + HID * STR;                            // [HID][STR]
    float4* wcs = reinterpret_cast<float4*>(vs + HID * STR); // [HID] (w,w,c,0)

    const int tid = threadIdx.x;
    const int i0 = blockIdx.y * 32;
    const int j0 = blockIdx.x * 64;

    for (int idx = tid; idx < 32 * HID; idx += 256) {
        int r = idx >> 7, h = idx & 127;
        float uv = g_u[(size_t)min(i0 + r, NN - 1) * HID + h];
        us[h * STR + 2 * r]     = uv;
        us[h * STR + 2 * r + 1] = uv;
    }
    for (int idx = tid; idx < 64 * HID; idx += 256) {
        int r = idx >> 7, h = idx & 127;
        vs[h * STR + r] = g_v[(size_t)min(j0 + r, NN - 1) * HID + h];
    }
    if (tid < HID) {
        float w = fc1_w[16 * HID + tid];
        wcs[tid] = make_float4(w, w, fc2_w[tid], 0.f);
    }
    __syncthreads();

    const int tj = tid & 15;
    const int ti = tid >> 4;
    const int gi = i0 + 2 * ti;
    const int gj = j0 + 4 * tj;
    const bool r0 = gi < NN, r1 = gi + 1 < NN, cj = gj < NN;

    float4 dz = make_float4(0.f, 0.f, 0.f, 0.f);
    float4 dA = (r0 && cj) ? *reinterpret_cast<const float4*>(dist + (size_t)gi * NN + gj) : dz;
    float4 dB = (r1 && cj) ? *reinterpret_cast<const float4*>(dist + (size_t)(gi + 1) * NN + gj) : dz;
    const ull D00 = f2_pack(dA.x, dA.y), D01 = f2_pack(dA.z, dA.w);
    const ull D10 = f2_pack(dB.x, dB.y), D11 = f2_pack(dB.z, dB.w);

    float a00 = 0.f, a01 = 0.f, a02 = 0.f, a03 = 0.f;
    float a10 = 0.f, a11 = 0.f, a12 = 0.f, a13 = 0.f;

#pragma unroll 8
    for (int h = 0; h < HID; h++) {
        ulonglong2 U = *reinterpret_cast<const ulonglong2*>(&us[h * STR + 4 * ti]);
        ulonglong2 V = *reinterpret_cast<const ulonglong2*>(&vs[h * STR + 4 * tj]);
        float4 wc = wcs[h];
        ull w2 = f2_pack(wc.x, wc.y);
        float ch = wc.z;
        ull p;
        p = f2_fma(D00, w2, f2_add(U.x, V.x)); relu_acc(p, ch, a00, a01);
        p = f2_fma(D01, w2, f2_add(U.x, V.y)); relu_acc(p, ch, a02, a03);
        p = f2_fma(D10, w2, f2_add(U.y, V.x)); relu_acc(p, ch, a10, a11);
        p = f2_fma(D11, w2, f2_add(U.y, V.y)); relu_acc(p, ch, a12, a13);
    }

    const float b = fc2_b[0];
    if (r0 && cj)
        *reinterpret_cast<float4*>(out + (size_t)gi * NN + gj) =
            make_float4(a00 + b, a01 + b, a02 + b, a03 + b);
    if (r1 && cj)
        *reinterpret_cast<float4*>(out + (size_t)(gi + 1) * NN + gj) =
            make_float4(a10 + b, a11 + b, a12 + b, a13 + b);
}

// ---------------- launch ------------------------------------------------------
extern "C" void kernel_launch(void* const* d_in, const int* in_sizes, int n_in,
                              void* d_out, int out_size) {
    const float* geo      = (const float*)d_in[0];
    const float* sem      = (const float*)d_in[1];
    const float* features = (const float*)d_in[2];
    // d_in[3] = region_pairs (int64) — exact meshgrid order, implicit indexing.
    const float* dist     = (const float*)d_in[4];
    const float* W0       = (const float*)d_in[5];
    const float* W1       = (const float*)d_in[6];
    const float* W2       = (const float*)d_in[7];
    const float* a0       = (const float*)d_in[8];
    const float* a1       = (const float*)d_in[9];
    const float* a2       = (const float*)d_in[10];
    const float* fc1_w    = (const float*)d_in[11];
    const float* fc1_b    = (const float*)d_in[12];
    const float* fc2_w    = (const float*)d_in[13];
    const float* fc2_b    = (const float*)d_in[14];
    float* out            = (float*)d_out;

    const int smem_pairs = HID * STR * 2 * 4 + HID * 16;  // ~72 KB
    cudaFuncSetAttribute(k_pairs, cudaFuncAttributeMaxDynamicSharedMemorySize,
                         smem_pairs);

    k_fused<<<NBLK, NTHR>>>((const float4*)geo, (const float4*)sem, features,
                            W0, a0, W1, a1, W2, a2, fc1_w, fc1_b);

    dim3 grid((NN + 63) / 64, (NN + 31) / 32);
    k_pairs<<<grid, 256, smem_pairs>>>(dist, fc1_w, fc2_w, fc2_b, out);
}

// round 6
// speedup vs baseline: 1.2671x; 1.2671x over previous
#include <cuda_runtime.h>
#include <math.h>
#include <float.h>

#define NN     1500
#define GIN    32
#define GOUT   8
#define HID    128
#define CAP    128          // max nnz per combined-adjacency row (mean ~60)
#define LALPHA 0.2f
#define USTR   68           // us smem row stride (floats), 64 data + pad
#define VSTR   132          // vs smem row stride (floats), 128 data + pad

typedef unsigned long long ull;

// ---------------- scratch (device globals) ----------------------------------
__device__ int      g_cnt[NN];
__device__ unsigned g_cols[NN * CAP];       // col | (a==2 ? bit31 : 0)
__device__ float    g_enc[NN * GOUT];       // final GAT output
__device__ float    g_h[2][NN * GOUT];      // ping-pong transformed feats
__device__ float    g_fsrc[2][NN];
__device__ float    g_fdst[2][NN];
__device__ float    g_uT[HID * NN + 64];    // transposed: [h][i], +pad for tile OOB
__device__ float    g_vT[HID * NN + 64];

// ---------------- f32x2 packed helpers --------------------------------------
__device__ __forceinline__ ull f2_pack(float lo, float hi) {
    ull r; asm("mov.b64 %0, {%1, %2};" : "=l"(r) : "f"(lo), "f"(hi)); return r;
}
__device__ __forceinline__ ull f2_add(ull a, ull b) {
    ull r; asm("add.rn.f32x2 %0, %1, %2;" : "=l"(r) : "l"(a), "l"(b)); return r;
}
__device__ __forceinline__ ull f2_fma(ull a, ull b, ull c) {
    ull r; asm("fma.rn.f32x2 %0, %1, %2, %3;" : "=l"(r) : "l"(a), "l"(b), "l"(c)); return r;
}
__device__ __forceinline__ void relu_acc(ull p, float c, float& a0, float& a1) {
    float lo = __uint_as_float((unsigned)p);
    float hi = __uint_as_float((unsigned)(p >> 32));
    a0 = fmaf(fmaxf(lo, 0.f), c, a0);
    a1 = fmaf(fmaxf(hi, 0.f), c, a1);
}

// ---------------- 1) deterministic sparse adjacency build -------------------
__global__ void k_build(const float4* __restrict__ geo,
                        const float4* __restrict__ sem) {
    const int i = blockIdx.x;
    const int tid = threadIdx.x;             // 128
    const float4* g = geo + (size_t)i * (NN / 4);
    const float4* s = sem + (size_t)i * (NN / 4);

    int c = 0;
#pragma unroll
    for (int k = 0; k < 3; k++) {
        int f = tid + k * 128;
        if (f < NN / 4) {
            float4 a = g[f], b = s[f];
            c += (a.x + b.x > 0.f) + (a.y + b.y > 0.f) +
                 (a.z + b.z > 0.f) + (a.w + b.w > 0.f);
        }
    }
    int lane = tid & 31, wid = tid >> 5;
    int x = c;
#pragma unroll
    for (int o = 1; o < 32; o <<= 1) {
        int y = __shfl_up_sync(0xFFFFFFFFu, x, o);
        if (lane >= o) x += y;
    }
    __shared__ int wsum[4];
    if (lane == 31) wsum[wid] = x;
    __syncthreads();
    int base = 0;
    for (int k = 0; k < wid; k++) base += wsum[k];
    int off = base + x - c;
    if (tid == 0) {
        int tot = wsum[0] + wsum[1] + wsum[2] + wsum[3];
        g_cnt[i] = min(tot, CAP);
    }
    unsigned* dst = g_cols + (size_t)i * CAP;
#pragma unroll
    for (int k = 0; k < 3; k++) {
        int f = tid + k * 128;
        if (f < NN / 4) {
            float4 a = g[f], b = s[f];
            float v[4] = {a.x + b.x, a.y + b.y, a.z + b.z, a.w + b.w};
#pragma unroll
            for (int c4 = 0; c4 < 4; c4++) {
                if (v[c4] > 0.f) {
                    if (off < CAP)
                        dst[off] = (unsigned)(f * 4 + c4) |
                                   (v[c4] >= 1.5f ? 0x80000000u : 0u);
                    off++;
                }
            }
        }
    }
}

// ---------------- 2) layer-0 transform ---------------------------------------
__global__ void k_t0(const float* __restrict__ feats,
                     const float* __restrict__ W,
                     const float* __restrict__ a) {
    int t = blockIdx.x * blockDim.x + threadIdx.x;
    int i0 = t >> 3;
    int c  = t & 7;
    int i  = min(i0, NN - 1);
    float acc = 0.f;
#pragma unroll
    for (int k = 0; k < GIN; k++)
        acc = fmaf(feats[i * GIN + k], W[k * GOUT + c], acc);
    float fs = acc * a[c];
    float fd = acc * a[GOUT + c];
#pragma unroll
    for (int off = 4; off > 0; off >>= 1) {
        fs += __shfl_xor_sync(0xFFFFFFFFu, fs, off);
        fd += __shfl_xor_sync(0xFFFFFFFFu, fd, off);
    }
    if (i0 < NN) {
        g_h[0][i * GOUT + c] = acc;
        if (c == 0) { g_fsrc[0][i] = fs; g_fdst[0][i] = fd; }
    }
}

// ---------------- 3) sparse GAT layer (warp per row) -------------------------
template <bool LAST>
__global__ void k_gats(int hsrc, int hdst,
                       const float* __restrict__ Wn,
                       const float* __restrict__ an) {
    const int lane = threadIdx.x & 31;
    const int i = blockIdx.x * 4 + (threadIdx.x >> 5);
    if (i >= NN) return;

    const float fsrc = g_fsrc[hsrc][i];
    const float* __restrict__ fdst = g_fdst[hsrc];
    const float* __restrict__ hbuf = g_h[hsrc];
    const int cnt = g_cnt[i];
    const unsigned* __restrict__ cols = g_cols + (size_t)i * CAP;

    float e[4]; int jj[4];
    float m = -FLT_MAX;
#pragma unroll
    for (int k = 0; k < 4; k++) {
        int idx = lane + k * 32;
        jj[k] = -1; e[k] = 0.f;
        if (idx < cnt) {
            unsigned pc = cols[idx];
            int j = pc & 0x7FFFFFFF;
            float a = (pc & 0x80000000u) ? 2.f : 1.f;
            float t = fsrc + fdst[j];
            float le = (t > 0.f ? t : LALPHA * t) * a;
            e[k] = le; jj[k] = j;
            m = fmaxf(m, le);
        }
    }
#pragma unroll
    for (int o = 16; o > 0; o >>= 1)
        m = fmaxf(m, __shfl_xor_sync(0xFFFFFFFFu, m, o));

    float s = 0.f, acc[GOUT];
#pragma unroll
    for (int q = 0; q < GOUT; q++) acc[q] = 0.f;
#pragma unroll
    for (int k = 0; k < 4; k++) {
        if (jj[k] >= 0) {
            float p = expf(e[k] - m);
            s += p;
            const float4* hp = reinterpret_cast<const float4*>(hbuf + jj[k] * GOUT);
            float4 h0 = hp[0], h1 = hp[1];
            acc[0] = fmaf(p, h0.x, acc[0]); acc[1] = fmaf(p, h0.y, acc[1]);
            acc[2] = fmaf(p, h0.z, acc[2]); acc[3] = fmaf(p, h0.w, acc[3]);
            acc[4] = fmaf(p, h1.x, acc[4]); acc[5] = fmaf(p, h1.y, acc[5]);
            acc[6] = fmaf(p, h1.z, acc[6]); acc[7] = fmaf(p, h1.w, acc[7]);
        }
    }
#pragma unroll
    for (int o = 16; o > 0; o >>= 1) {
        s += __shfl_xor_sync(0xFFFFFFFFu, s, o);
#pragma unroll
        for (int q = 0; q < GOUT; q++)
            acc[q] += __shfl_xor_sync(0xFFFFFFFFu, acc[q], o);
    }

    float inv = 1.f / s;
    float enc[GOUT];
#pragma unroll
    for (int q = 0; q < GOUT; q++) {
        float v = acc[q] * inv;
        enc[q] = (v > 0.f) ? v : expm1f(v);   // elu
    }

    if (LAST) {
        if (lane < GOUT) g_enc[i * GOUT + lane] = enc[lane];
    } else {
        if (lane < GOUT) {
            float hn = 0.f;
#pragma unroll
            for (int k = 0; k < GOUT; k++)
                hn = fmaf(enc[k], Wn[k * GOUT + lane], hn);
            g_h[hdst][i * GOUT + lane] = hn;
            float fs = hn * an[lane];
            float fd = hn * an[GOUT + lane];
#pragma unroll
            for (int o = 4; o > 0; o >>= 1) {
                fs += __shfl_xor_sync(0x000000FFu, fs, o);
                fd += __shfl_xor_sync(0x000000FFu, fd, o);
            }
            if (lane == 0) { g_fsrc[hdst][i] = fs; g_fdst[hdst][i] = fd; }
        }
    }
}

// ---------------- 4) rank-split precompute, TRANSPOSED output ----------------
// Block per hidden channel h; threads stride over nodes i. Writes g_uT[h][i].
__global__ void k_prep(const float* __restrict__ fc1_w,
                       const float* __restrict__ fc1_b) {
    const int h = blockIdx.x;                 // 0..127
    float wu[GOUT], wv[GOUT];
#pragma unroll
    for (int k = 0; k < GOUT; k++) {
        wu[k] = fc1_w[k * HID + h];
        wv[k] = fc1_w[(GOUT + k) * HID + h];
    }
    const float bu = fc1_b[h];
    for (int i = threadIdx.x; i < NN; i += blockDim.x) {
        const float4* ep = reinterpret_cast<const float4*>(g_enc + i * GOUT);
        float4 e0 = ep[0], e1 = ep[1];
        float ev[8] = {e0.x, e0.y, e0.z, e0.w, e1.x, e1.y, e1.z, e1.w};
        float u = bu, v = 0.f;
#pragma unroll
        for (int k = 0; k < GOUT; k++) {
            u = fmaf(ev[k], wu[k], u);
            v = fmaf(ev[k], wv[k], v);
        }
        g_uT[h * NN + i] = u;
        g_vT[h * NN + i] = v;
    }
}

// ---------------- 5) pair MLP: out = relu(u_i + v_j + d*w) . c + b ----------
// CTA tile 64 i x 128 j, 256 threads (16 i-groups x 16 j-groups),
// 4x8 pairs per thread. Per h: 4 LDS for 32 pairs (1.75 B/pair).
__global__ __launch_bounds__(256, 1) void k_pairs(const float* __restrict__ dist,
                                                  const float* __restrict__ fc1_w,
                                                  const float* __restrict__ fc2_w,
                                                  const float* __restrict__ fc2_b,
                                                  float* __restrict__ out) {
    extern __shared__ __align__(16) char smem_raw[];
    float*  us  = reinterpret_cast<float*>(smem_raw);        // [HID][USTR]
    float*  vs  = us + HID * USTR;                           // [HID][VSTR]
    float2* wcs = reinterpret_cast<float2*>(vs + HID * VSTR);// [HID] (w, c)

    const int tid = threadIdx.x;
    const int i0 = blockIdx.y * 64;
    const int j0 = blockIdx.x * 128;

    // fills: contiguous float4 rows from transposed gmem -> conflict-free
    for (int idx = tid; idx < HID * 16; idx += 256) {        // u: 64 floats/h
        int h = idx >> 4, c = idx & 15;
        *reinterpret_cast<float4*>(us + h * USTR + 4 * c) =
            *reinterpret_cast<const float4*>(g_uT + (size_t)h * NN + i0 + 4 * c);
    }
    for (int idx = tid; idx < HID * 32; idx += 256) {        // v: 128 floats/h
        int h = idx >> 5, c = idx & 31;
        *reinterpret_cast<float4*>(vs + h * VSTR + 4 * c) =
            *reinterpret_cast<const float4*>(g_vT + (size_t)h * NN + j0 + 4 * c);
    }
    if (tid < HID)
        wcs[tid] = make_float2(fc1_w[16 * HID + tid], fc2_w[tid]);
    __syncthreads();

    const int jg = tid & 15;                 // j group: 8 cols
    const int ig = tid >> 4;                 // i group: 4 rows
    const int gi = i0 + 4 * ig;
    const int gj = j0 + 8 * jg;
    const bool cA = gj < NN;                 // first float4 of j-block valid
    const bool cB = gj + 7 < NN;             // second float4 valid

    // distance tile: 4 rows x 8 cols, packed f32x2
    ull D[4][4];
#pragma unroll
    for (int r = 0; r < 4; r++) {
        const float4 dz = make_float4(0.f, 0.f, 0.f, 0.f);
        bool rv = (gi + r) < NN;
        float4 da = (rv && cA) ? *reinterpret_cast<const float4*>(dist + (size_t)(gi + r) * NN + gj) : dz;
        float4 db = (rv && cB) ? *reinterpret_cast<const float4*>(dist + (size_t)(gi + r) * NN + gj + 4) : dz;
        D[r][0] = f2_pack(da.x, da.y); D[r][1] = f2_pack(da.z, da.w);
        D[r][2] = f2_pack(db.x, db.y); D[r][3] = f2_pack(db.z, db.w);
    }

    float acc[4][8];
#pragma unroll
    for (int r = 0; r < 4; r++)
#pragma unroll
        for (int q = 0; q < 8; q++) acc[r][q] = 0.f;

#pragma unroll 2
    for (int h = 0; h < HID; h++) {
        const float4 u4 = *reinterpret_cast<const float4*>(us + h * USTR + 4 * ig);
        const float4 va = *reinterpret_cast<const float4*>(vs + h * VSTR + 8 * jg);
        const float4 vb = *reinterpret_cast<const float4*>(vs + h * VSTR + 8 * jg + 4);
        const float2 wc = wcs[h];
        const ull w2 = f2_pack(wc.x, wc.x);
        const float ch = wc.y;
        ull uu[4] = {f2_pack(u4.x, u4.x), f2_pack(u4.y, u4.y),
                     f2_pack(u4.z, u4.z), f2_pack(u4.w, u4.w)};
        ull vv[4] = {f2_pack(va.x, va.y), f2_pack(va.z, va.w),
                     f2_pack(vb.x, vb.y), f2_pack(vb.z, vb.w)};
#pragma unroll
        for (int r = 0; r < 4; r++) {
#pragma unroll
            for (int q = 0; q < 4; q++) {
                ull p = f2_fma(D[r][q], w2, f2_add(uu[r], vv[q]));
                relu_acc(p, ch, acc[r][2 * q], acc[r][2 * q + 1]);
            }
        }
    }

    const float b = fc2_b[0];
#pragma unroll
    for (int r = 0; r < 4; r++) {
        if (gi + r < NN) {
            float* o = out + (size_t)(gi + r) * NN + gj;
            if (cA)
                *reinterpret_cast<float4*>(o) =
                    make_float4(acc[r][0] + b, acc[r][1] + b, acc[r][2] + b, acc[r][3] + b);
            if (cB)
                *reinterpret_cast<float4*>(o + 4) =
                    make_float4(acc[r][4] + b, acc[r][5] + b, acc[r][6] + b, acc[r][7] + b);
        }
    }
}

// ---------------- launch ------------------------------------------------------
extern "C" void kernel_launch(void* const* d_in, const int* in_sizes, int n_in,
                              void* d_out, int out_size) {
    const float* geo      = (const float*)d_in[0];
    const float* sem      = (const float*)d_in[1];
    const float* features = (const float*)d_in[2];
    // d_in[3] = region_pairs (int64) — exact meshgrid order, implicit indexing.
    const float* dist     = (const float*)d_in[4];
    const float* W0       = (const float*)d_in[5];
    const float* W1       = (const float*)d_in[6];
    const float* W2       = (const float*)d_in[7];
    const float* a0       = (const float*)d_in[8];
    const float* a1       = (const float*)d_in[9];
    const float* a2       = (const float*)d_in[10];
    const float* fc1_w    = (const float*)d_in[11];
    const float* fc1_b    = (const float*)d_in[12];
    const float* fc2_w    = (const float*)d_in[13];
    const float* fc2_b    = (const float*)d_in[14];
    float* out            = (float*)d_out;

    const int smem_pairs = (HID * USTR + HID * VSTR) * 4 + HID * 8;  // ~101 KB
    cudaFuncSetAttribute(k_pairs, cudaFuncAttributeMaxDynamicSharedMemorySize,
                         smem_pairs);

    k_build<<<NN, 128>>>((const float4*)geo, (const float4*)sem);
    k_t0<<<(NN * GOUT + 255) / 256, 256>>>(features, W0, a0);
    k_gats<false><<<(NN + 3) / 4, 128>>>(0, 1, W1, a1);
    k_gats<false><<<(NN + 3) / 4, 128>>>(1, 0, W2, a2);
    k_gats<true><<<(NN + 3) / 4, 128>>>(0, 1, nullptr, nullptr);
    k_prep<<<HID, 256>>>(fc1_w, fc1_b);

    dim3 grid((NN + 127) / 128, (NN + 63) / 64);
    k_pairs<<<grid, 256, smem_pairs>>>(dist, fc1_w, fc2_w, fc2_b, out);
}

// round 8
// speedup vs baseline: 1.3047x; 1.0296x over previous
#include <cuda_runtime.h>
#include <math.h>
#include <float.h>

#define NN     1500
#define GIN    32
#define GOUT   8
#define HID    128
#define CAP    128          // max nnz per combined-adjacency row (mean ~60)
#define LALPHA 0.2f
#define USTR   68           // us smem row stride (floats), 64 data + pad
#define VSTR   132          // vs smem row stride (floats), 128 data + pad

typedef unsigned long long ull;

// ---------------- scratch (device globals) ----------------------------------
__device__ int      g_cnt[NN];
__device__ unsigned g_cols[NN * CAP];       // col | (a==2 ? bit31 : 0)
__device__ float    g_enc[NN * GOUT];       // final GAT output
__device__ float    g_h[2][NN * GOUT];      // ping-pong transformed feats
__device__ float    g_fsrc[2][NN];
__device__ float    g_fdst[2][NN];
__device__ float    g_uT[HID * NN + 64];    // transposed: [h][i], +pad for tile OOB
__device__ float    g_vT[HID * NN + 64];

// ---------------- f32x2 packed helpers --------------------------------------
__device__ __forceinline__ ull f2_pack(float lo, float hi) {
    ull r; asm("mov.b64 %0, {%1, %2};" : "=l"(r) : "f"(lo), "f"(hi)); return r;
}
__device__ __forceinline__ ull f2_add(ull a, ull b) {
    ull r; asm("add.rn.f32x2 %0, %1, %2;" : "=l"(r) : "l"(a), "l"(b)); return r;
}
__device__ __forceinline__ ull f2_fma(ull a, ull b, ull c) {
    ull r; asm("fma.rn.f32x2 %0, %1, %2, %3;" : "=l"(r) : "l"(a), "l"(b), "l"(c)); return r;
}
__device__ __forceinline__ void relu_acc(ull p, float c, float& a0, float& a1) {
    float lo = __uint_as_float((unsigned)p);
    float hi = __uint_as_float((unsigned)(p >> 32));
    a0 = fmaf(fmaxf(lo, 0.f), c, a0);
    a1 = fmaf(fmaxf(hi, 0.f), c, a1);
}

// ---------------- 1) sparse adjacency build + layer-0 transform -------------
__global__ void k_build(const float4* __restrict__ geo,
                        const float4* __restrict__ sem,
                        const float* __restrict__ feats,
                        const float* __restrict__ W0,
                        const float* __restrict__ a0) {
    const int i = blockIdx.x;
    const int tid = threadIdx.x;             // 128
    const float4* g = geo + (size_t)i * (NN / 4);
    const float4* s = sem + (size_t)i * (NN / 4);

    int c = 0;
#pragma unroll
    for (int k = 0; k < 3; k++) {
        int f = tid + k * 128;
        if (f < NN / 4) {
            float4 a = g[f], b = s[f];
            c += (a.x + b.x > 0.f) + (a.y + b.y > 0.f) +
                 (a.z + b.z > 0.f) + (a.w + b.w > 0.f);
        }
    }
    int lane = tid & 31, wid = tid >> 5;
    int x = c;
#pragma unroll
    for (int o = 1; o < 32; o <<= 1) {
        int y = __shfl_up_sync(0xFFFFFFFFu, x, o);
        if (lane >= o) x += y;
    }
    __shared__ int wsum[4];
    if (lane == 31) wsum[wid] = x;
    __syncthreads();
    int base = 0;
    for (int k = 0; k < wid; k++) base += wsum[k];
    int off = base + x - c;
    if (tid == 0) {
        int tot = wsum[0] + wsum[1] + wsum[2] + wsum[3];
        g_cnt[i] = min(tot, CAP);
    }
    unsigned* dst = g_cols + (size_t)i * CAP;
#pragma unroll
    for (int k = 0; k < 3; k++) {
        int f = tid + k * 128;
        if (f < NN / 4) {
            float4 a = g[f], b = s[f];
            float v[4] = {a.x + b.x, a.y + b.y, a.z + b.z, a.w + b.w};
#pragma unroll
            for (int c4 = 0; c4 < 4; c4++) {
                if (v[c4] > 0.f) {
                    if (off < CAP)
                        dst[off] = (unsigned)(f * 4 + c4) |
                                   (v[c4] >= 1.5f ? 0x80000000u : 0u);
                    off++;
                }
            }
        }
    }

    // fused layer-0 transform (lanes 0-7 of warp 0): h0 = feats[i] @ W0
    if (tid < GOUT) {
        float acc = 0.f;
#pragma unroll
        for (int k = 0; k < GIN; k++)
            acc = fmaf(feats[i * GIN + k], W0[k * GOUT + tid], acc);
        g_h[0][i * GOUT + tid] = acc;
        float fs = acc * a0[tid];
        float fd = acc * a0[GOUT + tid];
#pragma unroll
        for (int o = 4; o > 0; o >>= 1) {
            fs += __shfl_xor_sync(0x000000FFu, fs, o);
            fd += __shfl_xor_sync(0x000000FFu, fd, o);
        }
        if (tid == 0) { g_fsrc[0][i] = fs; g_fdst[0][i] = fd; }
    }
}

// ---------------- 2) sparse GAT layer (warp per row) -------------------------
template <bool LAST>
__global__ void k_gats(int hsrc, int hdst,
                       const float* __restrict__ Wn,
                       const float* __restrict__ an) {
    const int lane = threadIdx.x & 31;
    const int i = blockIdx.x * 4 + (threadIdx.x >> 5);
    if (i >= NN) return;

    const float fsrc = g_fsrc[hsrc][i];
    const float* __restrict__ fdst = g_fdst[hsrc];
    const float* __restrict__ hbuf = g_h[hsrc];
    const int cnt = g_cnt[i];
    const unsigned* __restrict__ cols = g_cols + (size_t)i * CAP;

    float e[4]; int jj[4];
    float m = -FLT_MAX;
#pragma unroll
    for (int k = 0; k < 4; k++) {
        int idx = lane + k * 32;
        jj[k] = -1; e[k] = 0.f;
        if (idx < cnt) {
            unsigned pc = cols[idx];
            int j = pc & 0x7FFFFFFF;
            float a = (pc & 0x80000000u) ? 2.f : 1.f;
            float t = fsrc + fdst[j];
            float le = (t > 0.f ? t : LALPHA * t) * a;
            e[k] = le; jj[k] = j;
            m = fmaxf(m, le);
        }
    }
#pragma unroll
    for (int o = 16; o > 0; o >>= 1)
        m = fmaxf(m, __shfl_xor_sync(0xFFFFFFFFu, m, o));

    float s = 0.f, acc[GOUT];
#pragma unroll
    for (int q = 0; q < GOUT; q++) acc[q] = 0.f;
#pragma unroll
    for (int k = 0; k < 4; k++) {
        if (jj[k] >= 0) {
            float p = expf(e[k] - m);
            s += p;
            const float4* hp = reinterpret_cast<const float4*>(hbuf + jj[k] * GOUT);
            float4 h0 = hp[0], h1 = hp[1];
            acc[0] = fmaf(p, h0.x, acc[0]); acc[1] = fmaf(p, h0.y, acc[1]);
            acc[2] = fmaf(p, h0.z, acc[2]); acc[3] = fmaf(p, h0.w, acc[3]);
            acc[4] = fmaf(p, h1.x, acc[4]); acc[5] = fmaf(p, h1.y, acc[5]);
            acc[6] = fmaf(p, h1.z, acc[6]); acc[7] = fmaf(p, h1.w, acc[7]);
        }
    }
#pragma unroll
    for (int o = 16; o > 0; o >>= 1) {
        s += __shfl_xor_sync(0xFFFFFFFFu, s, o);
#pragma unroll
        for (int q = 0; q < GOUT; q++)
            acc[q] += __shfl_xor_sync(0xFFFFFFFFu, acc[q], o);
    }

    float inv = 1.f / s;
    float enc[GOUT];
#pragma unroll
    for (int q = 0; q < GOUT; q++) {
        float v = acc[q] * inv;
        enc[q] = (v > 0.f) ? v : expm1f(v);   // elu
    }

    if (LAST) {
        if (lane < GOUT) g_enc[i * GOUT + lane] = enc[lane];
    } else {
        if (lane < GOUT) {
            float hn = 0.f;
#pragma unroll
            for (int k = 0; k < GOUT; k++)
                hn = fmaf(enc[k], Wn[k * GOUT + lane], hn);
            g_h[hdst][i * GOUT + lane] = hn;
            float fs = hn * an[lane];
            float fd = hn * an[GOUT + lane];
#pragma unroll
            for (int o = 4; o > 0; o >>= 1) {
                fs += __shfl_xor_sync(0x000000FFu, fs, o);
                fd += __shfl_xor_sync(0x000000FFu, fd, o);
            }
            if (lane == 0) { g_fsrc[hdst][i] = fs; g_fdst[hdst][i] = fd; }
        }
    }
}

// ---------------- 3) rank-split precompute, TRANSPOSED output ----------------
__global__ void k_prep(const float* __restrict__ fc1_w,
                       const float* __restrict__ fc1_b) {
    const int h = blockIdx.x;                 // 0..127
    float wu[GOUT], wv[GOUT];
#pragma unroll
    for (int k = 0; k < GOUT; k++) {
        wu[k] = fc1_w[k * HID + h];
        wv[k] = fc1_w[(GOUT + k) * HID + h];
    }
    const float bu = fc1_b[h];
    for (int i = threadIdx.x; i < NN; i += blockDim.x) {
        const float4* ep = reinterpret_cast<const float4*>(g_enc + i * GOUT);
        float4 e0 = ep[0], e1 = ep[1];
        float ev[8] = {e0.x, e0.y, e0.z, e0.w, e1.x, e1.y, e1.z, e1.w};
        float u = bu, v = 0.f;
#pragma unroll
        for (int k = 0; k < GOUT; k++) {
            u = fmaf(ev[k], wu[k], u);
            v = fmaf(ev[k], wv[k], v);
        }
        g_uT[h * NN + i] = u;
        g_vT[h * NN + i] = v;
    }
}

// ---------------- 4) pair MLP: out = relu(u_i + v_j + d*w) . c + b ----------
// CTA tile 64 i x 128 j, 256 threads, 4x8 pairs/thread. 2 CTAs/SM (206 KB of
// the 228 KB carveout) -> 4 warps/SMSP for latency hiding; grid 288 <= 296
// (single wave).
__global__ __launch_bounds__(256, 2) void k_pairs(const float* __restrict__ dist,
                                                  const float* __restrict__ fc1_w,
                                                  const float* __restrict__ fc2_w,
                                                  const float* __restrict__ fc2_b,
                                                  float* __restrict__ out) {
    extern __shared__ __align__(16) char smem_raw[];
    float*  us  = reinterpret_cast<float*>(smem_raw);        // [HID][USTR]
    float*  vs  = us + HID * USTR;                           // [HID][VSTR]
    float2* wcs = reinterpret_cast<float2*>(vs + HID * VSTR);// [HID] (w, c)

    const int tid = threadIdx.x;
    const int i0 = blockIdx.y * 64;
    const int j0 = blockIdx.x * 128;

    for (int idx = tid; idx < HID * 16; idx += 256) {        // u: 64 floats/h
        int h = idx >> 4, c = idx & 15;
        *reinterpret_cast<float4*>(us + h * USTR + 4 * c) =
            *reinterpret_cast<const float4*>(g_uT + (size_t)h * NN + i0 + 4 * c);
    }
    for (int idx = tid; idx < HID * 32; idx += 256) {        // v: 128 floats/h
        int h = idx >> 5, c = idx & 31;
        *reinterpret_cast<float4*>(vs + h * VSTR + 4 * c) =
            *reinterpret_cast<const float4*>(g_vT + (size_t)h * NN + j0 + 4 * c);
    }
    if (tid < HID)
        wcs[tid] = make_float2(fc1_w[16 * HID + tid], fc2_w[tid]);
    __syncthreads();

    const int jg = tid & 15;                 // j group: 8 cols
    const int ig = tid >> 4;                 // i group: 4 rows
    const int gi = i0 + 4 * ig;
    const int gj = j0 + 8 * jg;
    const bool cA = gj < NN;
    const bool cB = gj + 7 < NN;

    ull D[4][4];
#pragma unroll
    for (int r = 0; r < 4; r++) {
        const float4 dz = make_float4(0.f, 0.f, 0.f, 0.f);
        bool rv = (gi + r) < NN;
        float4 da = (rv && cA) ? *reinterpret_cast<const float4*>(dist + (size_t)(gi + r) * NN + gj) : dz;
        float4 db = (rv && cB) ? *reinterpret_cast<const float4*>(dist + (size_t)(gi + r) * NN + gj + 4) : dz;
        D[r][0] = f2_pack(da.x, da.y); D[r][1] = f2_pack(da.z, da.w);
        D[r][2] = f2_pack(db.x, db.y); D[r][3] = f2_pack(db.z, db.w);
    }

    float acc[4][8];
#pragma unroll
    for (int r = 0; r < 4; r++)
#pragma unroll
        for (int q = 0; q < 8; q++) acc[r][q] = 0.f;

#pragma unroll 2
    for (int h = 0; h < HID; h++) {
        const float4 u4 = *reinterpret_cast<const float4*>(us + h * USTR + 4 * ig);
        const float4 va = *reinterpret_cast<const float4*>(vs + h * VSTR + 8 * jg);
        const float4 vb = *reinterpret_cast<const float4*>(vs + h * VSTR + 8 * jg + 4);
        const float2 wc = wcs[h];
        const ull w2 = f2_pack(wc.x, wc.x);
        const float ch = wc.y;
        ull uu[4] = {f2_pack(u4.x, u4.x), f2_pack(u4.y, u4.y),
                     f2_pack(u4.z, u4.z), f2_pack(u4.w, u4.w)};
        ull vv[4] = {f2_pack(va.x, va.y), f2_pack(va.z, va.w),
                     f2_pack(vb.x, vb.y), f2_pack(vb.z, vb.w)};
#pragma unroll
        for (int r = 0; r < 4; r++) {
#pragma unroll
            for (int q = 0; q < 4; q++) {
                ull p = f2_fma(D[r][q], w2, f2_add(uu[r], vv[q]));
                relu_acc(p, ch, acc[r][2 * q], acc[r][2 * q + 1]);
            }
        }
    }

    const float b = fc2_b[0];
#pragma unroll
    for (int r = 0; r < 4; r++) {
        if (gi + r < NN) {
            float* o = out + (size_t)(gi + r) * NN + gj;
            if (cA)
                *reinterpret_cast<float4*>(o) =
                    make_float4(acc[r][0] + b, acc[r][1] + b, acc[r][2] + b, acc[r][3] + b);
            if (cB)
                *reinterpret_cast<float4*>(o + 4) =
                    make_float4(acc[r][4] + b, acc[r][5] + b, acc[r][6] + b, acc[r][7] + b);
        }
    }
}

// ---------------- launch ------------------------------------------------------
extern "C" void kernel_launch(void* const* d_in, const int* in_sizes, int n_in,
                              void* d_out, int out_size) {
    const float* geo      = (const float*)d_in[0];
    const float* sem      = (const float*)d_in[1];
    const float* features = (const float*)d_in[2];
    // d_in[3] = region_pairs (int64) — exact meshgrid order, implicit indexing.
    const float* dist     = (const float*)d_in[4];
    const float* W0       = (const float*)d_in[5];
    const float* W1       = (const float*)d_in[6];
    const float* W2       = (const float*)d_in[7];
    const float* a0       = (const float*)d_in[8];
    const float* a1       = (const float*)d_in[9];
    const float* a2       = (const float*)d_in[10];
    const float* fc1_w    = (const float*)d_in[11];
    const float* fc1_b    = (const float*)d_in[12];
    const float* fc2_w    = (const float*)d_in[13];
    const float* fc2_b    = (const float*)d_in[14];
    float* out            = (float*)d_out;

    const int smem_pairs = (HID * USTR + HID * VSTR) * 4 + HID * 8;  // ~103 KB
    cudaFuncSetAttribute(k_pairs, cudaFuncAttributeMaxDynamicSharedMemorySize,
                         smem_pairs);

    // launch idx 0..5; k_pairs is idx 5 (ncu -s 5 -c 1 profiles it)
    k_build<<<NN, 128>>>((const float4*)geo, (const float4*)sem,
                         features, W0, a0);
    k_gats<false><<<(NN + 3) / 4, 128>>>(0, 1, W1, a1);
    k_gats<false><<<(NN + 3) / 4, 128>>>(1, 0, W2, a2);
    k_gats<true><<<(NN + 3) / 4, 128>>>(0, 1, nullptr, nullptr);
    k_prep<<<HID, 256>>>(fc1_w, fc1_b);

    dim3 grid((NN + 127) / 128, (NN + 63) / 64);
    k_pairs<<<grid, 256, smem_pairs>>>(dist, fc1_w, fc2_w, fc2_b, out);
}